// round 4
// baseline (speedup 1.0000x reference)
#include <cuda_runtime.h>
#include <math.h>
#include <stdint.h>

#define BATCH 4
#define SEQ   4096
#define DMODEL 2048
#define HD    128
#define DV    256
#define MROWS (BATCH*SEQ)

__device__ float g_Q[MROWS * DV];
__device__ float g_K[MROWS * DV];
__device__ float g_V[MROWS * DV];

// ---------------------------------------------------------------------------
// tf32 helpers
// ---------------------------------------------------------------------------
__device__ __forceinline__ void tf32_split(float x, float& hi, float& lo) {
    float h;
    asm("cvt.rna.tf32.f32 %0, %1;" : "=f"(h) : "f"(x));
    hi = h;
    lo = x - h;
}
__device__ __forceinline__ void split4(float4 v, float4& h, float4& l) {
    tf32_split(v.x, h.x, l.x);
    tf32_split(v.y, h.y, l.y);
    tf32_split(v.z, h.z, l.z);
    tf32_split(v.w, h.w, l.w);
}

__device__ __forceinline__ void mma_m16n8k8(float c[4], const float a[4], const float b[2]) {
    asm volatile(
        "mma.sync.aligned.m16n8k8.row.col.f32.tf32.tf32.f32 "
        "{%0,%1,%2,%3}, {%4,%5,%6,%7}, {%8,%9}, {%0,%1,%2,%3};"
        : "+f"(c[0]), "+f"(c[1]), "+f"(c[2]), "+f"(c[3])
        : "r"(__float_as_uint(a[0])), "r"(__float_as_uint(a[1])),
          "r"(__float_as_uint(a[2])), "r"(__float_as_uint(a[3])),
          "r"(__float_as_uint(b[0])), "r"(__float_as_uint(b[1])));
}
__device__ __forceinline__ void mma3(float c[4], const float ah[4], const float al[4],
                                     const float bh[2], const float bl[2]) {
    mma_m16n8k8(c, ah, bh);
    mma_m16n8k8(c, al, bh);
    mma_m16n8k8(c, ah, bl);
}

// ---------------------------------------------------------------------------
// Kernel 1: projection GEMM with pre-split smem tiles.
// C = x @ W (M=16384, N=256, K=2048); CTA 128x128, 8 warps, BK=32.
// ---------------------------------------------------------------------------
#define PAP 36
#define PBP 136
#define PROJ_SMEM_FLOATS (128*PAP*2 + 32*PBP*2)
#define PROJ_SMEM_BYTES  (PROJ_SMEM_FLOATS * 4)

__global__ __launch_bounds__(256, 2) void proj_mma_kernel(
    const float* __restrict__ x, const float* __restrict__ WQ,
    const float* __restrict__ WK, const float* __restrict__ WV)
{
    extern __shared__ float ps[];
    float* AH = ps;
    float* AL = AH + 128 * PAP;
    float* BH = AL + 128 * PAP;
    float* BL = BH + 32 * PBP;

    const int tid = threadIdx.x;
    const int w   = tid >> 5, l = tid & 31;
    const int gid = l >> 2,  tig = l & 3;
    const int wr  = w >> 1,  wc  = w & 1;
    const int m0c = blockIdx.x * 128;
    const int n0c = blockIdx.y * 128;
    const float* __restrict__ W = (blockIdx.z == 0) ? WQ : (blockIdx.z == 1) ? WK : WV;
    float* __restrict__ C = (blockIdx.z == 0) ? g_Q : (blockIdx.z == 1) ? g_K : g_V;

    float acc[2][8][4];
#pragma unroll
    for (int mb = 0; mb < 2; mb++)
#pragma unroll
        for (int nb = 0; nb < 8; nb++)
#pragma unroll
            for (int i = 0; i < 4; i++) acc[mb][nb][i] = 0.f;

    for (int k0 = 0; k0 < DMODEL; k0 += 32) {
        __syncthreads();
        // stage A: 128 rows x 32 cols, split at STS
#pragma unroll
        for (int p = 0; p < 4; p++) {
            int row = p * 32 + (tid >> 3);
            int f4  = (tid & 7) * 4;
            float4 v = *(const float4*)&x[(size_t)(m0c + row) * DMODEL + k0 + f4];
            float4 h, lo;
            split4(v, h, lo);
            *(float4*)&AH[row * PAP + f4] = h;
            *(float4*)&AL[row * PAP + f4] = lo;
        }
        // stage B: 32 rows x 128 cols
#pragma unroll
        for (int p = 0; p < 4; p++) {
            int kr = p * 8 + (tid >> 5);
            int f4 = (tid & 31) * 4;
            float4 v = *(const float4*)&W[(size_t)(k0 + kr) * DV + n0c + f4];
            float4 h, lo;
            split4(v, h, lo);
            *(float4*)&BH[kr * PBP + f4] = h;
            *(float4*)&BL[kr * PBP + f4] = lo;
        }
        __syncthreads();

#pragma unroll
        for (int ks = 0; ks < 4; ks++) {
            float ah[2][4], al[2][4];
#pragma unroll
            for (int mb = 0; mb < 2; mb++) {
                int base = (wr * 32 + mb * 16 + gid) * PAP + ks * 8 + tig;
                ah[mb][0] = AH[base];            al[mb][0] = AL[base];
                ah[mb][1] = AH[base + 8 * PAP];  al[mb][1] = AL[base + 8 * PAP];
                ah[mb][2] = AH[base + 4];        al[mb][2] = AL[base + 4];
                ah[mb][3] = AH[base + 8 * PAP + 4]; al[mb][3] = AL[base + 8 * PAP + 4];
            }
#pragma unroll
            for (int nb = 0; nb < 8; nb++) {
                int bb = (ks * 8 + tig) * PBP + wc * 64 + nb * 8 + gid;
                float bh[2], bl[2];
                bh[0] = BH[bb];            bl[0] = BL[bb];
                bh[1] = BH[bb + 4 * PBP];  bl[1] = BL[bb + 4 * PBP];
                mma3(acc[0][nb], ah[0], al[0], bh, bl);
                mma3(acc[1][nb], ah[1], al[1], bh, bl);
            }
        }
    }

#pragma unroll
    for (int mb = 0; mb < 2; mb++) {
        int r0 = m0c + wr * 32 + mb * 16 + gid;
#pragma unroll
        for (int nb = 0; nb < 8; nb++) {
            int cc = n0c + wc * 64 + nb * 8 + 2 * tig;
            *(float2*)&C[(size_t)r0 * DV + cc]       = make_float2(acc[mb][nb][0], acc[mb][nb][1]);
            *(float2*)&C[(size_t)(r0 + 8) * DV + cc] = make_float2(acc[mb][nb][2], acc[mb][nb][3]);
        }
    }
}

// ---------------------------------------------------------------------------
// Kernel 2: flash differential attention, all operands pre-split in smem.
// ABM=32 q rows/CTA, ABN=32 keys/tile, 512 threads (16 warps).
// ---------------------------------------------------------------------------
#define ABM 32
#define ABN 32
#define ATHR 512
#define QP 260     // Q/K row pitch (stride mod 32 == 4)
#define VP 264     // V row pitch (stride mod 32 == 8)
#define PP 36      // P row pitch (stride mod 32 == 4)

// float offsets
#define SQH 0
#define SQL (SQH + ABM * QP)
#define SKH (SQL + ABM * QP)
#define SKL (SKH + ABN * QP)
#define SVH (SKL + ABN * QP)
#define SVL (SVH + ABN * VP)
#define SPH (SVL + ABN * VP)
#define SPL (SPH + 2 * ABM * PP)
#define SMR (SPL + 2 * ABM * PP)
#define SLR (SMR + 64)
#define SFR (SLR + 64)
#define SLAM (SFR + 64)
#define ATOT (SLAM + 4)
#define ATOT_BYTES (ATOT * 4)

__global__ __launch_bounds__(ATHR, 1) void diff_attn_mma(
    const float* __restrict__ lq1, const float* __restrict__ lq2,
    const float* __restrict__ lk1, const float* __restrict__ lk2,
    float* __restrict__ out)
{
    extern __shared__ float sm[];
    const int tid = threadIdx.x;
    const int w   = tid >> 5, l = tid & 31;
    const int gid = l >> 2,  tig = l & 3;
    const int b   = blockIdx.y;
    const int q0  = blockIdx.x * ABM;
    const float scale = 0.08838834764831845f;  // HD^-0.5

    // lambda scalar
    if (tid < 32) {
        float s1 = 0.f, s2 = 0.f;
        for (int i = l; i < HD; i += 32) {
            s1 += lq1[i] * lk1[i];
            s2 += lq2[i] * lk2[i];
        }
#pragma unroll
        for (int o = 16; o; o >>= 1) {
            s1 += __shfl_xor_sync(0xffffffffu, s1, o);
            s2 += __shfl_xor_sync(0xffffffffu, s2, o);
        }
        if (l == 0) {
            double li = 0.8 - 0.6 * exp(-3.6);
            sm[SLAM] = __expf(s1) + __expf(s2) + (float)li;
        }
    }
    if (tid < 64) { sm[SMR + tid] = -INFINITY; sm[SLR + tid] = 0.f; }

    // Q load + scale + split (once)
    for (int idx = tid; idx < ABM * 64; idx += ATHR) {
        int r = idx >> 6, f4 = idx & 63;
        float4 v = *(const float4*)&g_Q[(size_t)(b * SEQ + q0 + r) * DV + f4 * 4];
        v.x *= scale; v.y *= scale; v.z *= scale; v.w *= scale;
        float4 h, lo;
        split4(v, h, lo);
        *(float4*)&sm[SQH + r * QP + f4 * 4] = h;
        *(float4*)&sm[SQL + r * QP + f4 * 4] = lo;
    }

    // warp roles
    const int mat = w >> 3;          // 0 or 1 (score matrix / O accumulator)
    const int wl  = w & 7;
    const int qk_mt = wl >> 2;       // QK: m16 block 0/1
    const int qk_nt = wl & 3;        // QK: n8 block 0..3
    const int pv_mr = wl >> 2;       // PV: m16 block 0/1
    const int pv_nq = wl & 3;        // PV: 64-col quadrant

    float O[8][4];
#pragma unroll
    for (int nt = 0; nt < 8; nt++)
#pragma unroll
        for (int i = 0; i < 4; i++) O[nt][i] = 0.f;

    const int matP = SPH + mat * (ABM * PP);
    const int matPl = SPL + mat * (ABM * PP);

    for (int j0 = 0; j0 < SEQ; j0 += ABN) {
        __syncthreads();  // prev-tile consumers done; safe to overwrite K/V
        // K,V load + split
        for (int idx = tid; idx < ABN * 64; idx += ATHR) {
            int r = idx >> 6, f4 = idx & 63;
            size_t g = (size_t)(b * SEQ + j0 + r) * DV + f4 * 4;
            float4 kv = *(const float4*)&g_K[g];
            float4 vv = *(const float4*)&g_V[g];
            float4 h, lo;
            split4(kv, h, lo);
            *(float4*)&sm[SKH + r * QP + f4 * 4] = h;
            *(float4*)&sm[SKL + r * QP + f4 * 4] = lo;
            split4(vv, h, lo);
            *(float4*)&sm[SVH + r * VP + f4 * 4] = h;
            *(float4*)&sm[SVL + r * VP + f4 * 4] = lo;
        }
        __syncthreads();

        // QK^T: each warp one m16n8 score tile of its matrix (k = 128)
        {
            float c[4] = {0.f, 0.f, 0.f, 0.f};
            const int qbase = (qk_mt * 16 + gid) * QP + mat * 128;
            const int kbase = (qk_nt * 8 + gid) * QP + mat * 128;
#pragma unroll
            for (int ks = 0; ks < 16; ks++) {
                int ab = qbase + ks * 8 + tig;
                float ah[4], al[4];
                ah[0] = sm[SQH + ab];              al[0] = sm[SQL + ab];
                ah[1] = sm[SQH + ab + 8 * QP];     al[1] = sm[SQL + ab + 8 * QP];
                ah[2] = sm[SQH + ab + 4];          al[2] = sm[SQL + ab + 4];
                ah[3] = sm[SQH + ab + 8 * QP + 4]; al[3] = sm[SQL + ab + 8 * QP + 4];
                int bb = kbase + ks * 8 + tig;
                float bh[2], bl[2];
                bh[0] = sm[SKH + bb];     bl[0] = sm[SKL + bb];
                bh[1] = sm[SKH + bb + 4]; bl[1] = sm[SKL + bb + 4];
                mma3(c, ah, al, bh, bl);
            }
            int rr = qk_mt * 16 + gid;
            int cc = qk_nt * 8 + 2 * tig;
            *(float2*)&sm[matP + rr * PP + cc]       = make_float2(c[0], c[1]);
            *(float2*)&sm[matP + (rr + 8) * PP + cc] = make_float2(c[2], c[3]);
        }
        __syncthreads();

        // online softmax over 32 cols; 8 lanes per row, 4 cols each; split P
        {
            int smat = tid >> 8;
            int srow = (tid >> 3) & 31;
            int cb   = (tid & 7) * 4;
            int base = SPH + smat * (ABM * PP) + srow * PP + cb;
            float4 v = *(float4*)&sm[base];
            float tmax = fmaxf(fmaxf(v.x, v.y), fmaxf(v.z, v.w));
            tmax = fmaxf(tmax, __shfl_xor_sync(0xffffffffu, tmax, 1));
            tmax = fmaxf(tmax, __shfl_xor_sync(0xffffffffu, tmax, 2));
            tmax = fmaxf(tmax, __shfl_xor_sync(0xffffffffu, tmax, 4));
            float mold = sm[SMR + smat * 32 + srow];
            float mnew = fmaxf(mold, tmax);
            float4 e;
            e.x = __expf(v.x - mnew);
            e.y = __expf(v.y - mnew);
            e.z = __expf(v.z - mnew);
            e.w = __expf(v.w - mnew);
            float4 h, lo;
            split4(e, h, lo);
            *(float4*)&sm[base] = h;
            *(float4*)&sm[base + (SPL - SPH)] = lo;
            float sum = e.x + e.y + e.z + e.w;
            sum += __shfl_xor_sync(0xffffffffu, sum, 1);
            sum += __shfl_xor_sync(0xffffffffu, sum, 2);
            sum += __shfl_xor_sync(0xffffffffu, sum, 4);
            if ((tid & 7) == 0) {
                float f = __expf(mold - mnew);
                sm[SMR + smat * 32 + srow] = mnew;
                sm[SLR + smat * 32 + srow] = sm[SLR + smat * 32 + srow] * f + sum;
                sm[SFR + smat * 32 + srow] = f;
            }
        }
        __syncthreads();

        // PV: each warp m16 x 64 cols of O{mat}
        {
            float fa = sm[SFR + mat * 32 + pv_mr * 16 + gid];
            float fb = sm[SFR + mat * 32 + pv_mr * 16 + gid + 8];
#pragma unroll
            for (int nt = 0; nt < 8; nt++) {
                O[nt][0] *= fa; O[nt][1] *= fa; O[nt][2] *= fb; O[nt][3] *= fb;
            }
            const int pbase = (pv_mr * 16 + gid) * PP;
#pragma unroll
            for (int kk = 0; kk < 4; kk++) {
                int ab = pbase + kk * 8 + tig;
                float ah[4], al[4];
                ah[0] = sm[matP + ab];              al[0] = sm[matPl + ab];
                ah[1] = sm[matP + ab + 8 * PP];     al[1] = sm[matPl + ab + 8 * PP];
                ah[2] = sm[matP + ab + 4];          al[2] = sm[matPl + ab + 4];
                ah[3] = sm[matP + ab + 8 * PP + 4]; al[3] = sm[matPl + ab + 8 * PP + 4];
#pragma unroll
                for (int nt = 0; nt < 8; nt++) {
                    int col = pv_nq * 64 + nt * 8 + gid;
                    int b0 = (kk * 8 + tig) * VP + col;
                    int b1 = (kk * 8 + tig + 4) * VP + col;
                    float bh[2], bl[2];
                    bh[0] = sm[SVH + b0]; bl[0] = sm[SVL + b0];
                    bh[1] = sm[SVH + b1]; bl[1] = sm[SVL + b1];
                    mma3(O[nt], ah, al, bh, bl);
                }
            }
        }
    }
    __syncthreads();

    // epilogue: out = O1/l1 - lam*O2/l2 via smem scratch (reuse Q area)
    const float lam = sm[SLAM];
    const int ra = pv_mr * 16 + gid, rb = ra + 8;
    if (mat == 1) {
        float s2a = lam / sm[SLR + 32 + ra];
        float s2b = lam / sm[SLR + 32 + rb];
#pragma unroll
        for (int nt = 0; nt < 8; nt++) {
            int cc = pv_nq * 64 + nt * 8 + 2 * tig;
            *(float2*)&sm[SQH + ra * VP + cc] = make_float2(O[nt][0] * s2a, O[nt][1] * s2a);
            *(float2*)&sm[SQH + rb * VP + cc] = make_float2(O[nt][2] * s2b, O[nt][3] * s2b);
        }
    }
    __syncthreads();
    if (mat == 0) {
        float i1a = 1.f / sm[SLR + ra];
        float i1b = 1.f / sm[SLR + rb];
        size_t basea = (size_t)(b * SEQ + q0 + ra) * DV;
        size_t baseb = (size_t)(b * SEQ + q0 + rb) * DV;
#pragma unroll
        for (int nt = 0; nt < 8; nt++) {
            int cc = pv_nq * 64 + nt * 8 + 2 * tig;
            float2 s2 = *(float2*)&sm[SQH + ra * VP + cc];
            *(float2*)&out[basea + cc] = make_float2(O[nt][0] * i1a - s2.x, O[nt][1] * i1a - s2.y);
            s2 = *(float2*)&sm[SQH + rb * VP + cc];
            *(float2*)&out[baseb + cc] = make_float2(O[nt][2] * i1b - s2.x, O[nt][3] * i1b - s2.y);
        }
    }
}

// ---------------------------------------------------------------------------
// Launch
// ---------------------------------------------------------------------------
extern "C" void kernel_launch(void* const* d_in, const int* in_sizes, int n_in,
                              void* d_out, int out_size)
{
    const float* x   = (const float*)d_in[0];
    const float* WQ  = (const float*)d_in[1];
    const float* WK  = (const float*)d_in[2];
    const float* WV  = (const float*)d_in[3];
    const float* lq1 = (const float*)d_in[4];
    const float* lq2 = (const float*)d_in[5];
    const float* lk1 = (const float*)d_in[6];
    const float* lk2 = (const float*)d_in[7];
    float* out = (float*)d_out;

    cudaFuncSetAttribute(proj_mma_kernel,
                         cudaFuncAttributeMaxDynamicSharedMemorySize, PROJ_SMEM_BYTES);
    dim3 pgrid(MROWS / 128, DV / 128, 3);
    proj_mma_kernel<<<pgrid, 256, PROJ_SMEM_BYTES>>>(x, WQ, WK, WV);

    cudaFuncSetAttribute(diff_attn_mma,
                         cudaFuncAttributeMaxDynamicSharedMemorySize, ATOT_BYTES);
    dim3 agrid(SEQ / ABM, BATCH);
    diff_attn_mma<<<agrid, ATHR, ATOT_BYTES>>>(lq1, lq2, lk1, lk2, out);
}

// round 5
// speedup vs baseline: 1.3626x; 1.3626x over previous
#include <cuda_runtime.h>
#include <math.h>
#include <stdint.h>

#define BATCH 4
#define SEQ   4096
#define DMODEL 2048
#define HD    128
#define DV    256
#define MROWS (BATCH*SEQ)

__device__ float g_Q[MROWS * DV];
__device__ float g_K[MROWS * DV];
__device__ float g_V[MROWS * DV];

// ---------------------------------------------------------------------------
// tf32 helpers
// ---------------------------------------------------------------------------
__device__ __forceinline__ void tf32_split(float x, float& hi, float& lo) {
    float h;
    asm("cvt.rna.tf32.f32 %0, %1;" : "=f"(h) : "f"(x));
    hi = h;
    lo = x - h;
}
__device__ __forceinline__ float tf32_round(float x) {
    float h;
    asm("cvt.rna.tf32.f32 %0, %1;" : "=f"(h) : "f"(x));
    return h;
}
__device__ __forceinline__ void split4(float4 v, float4& h, float4& l) {
    tf32_split(v.x, h.x, l.x);
    tf32_split(v.y, h.y, l.y);
    tf32_split(v.z, h.z, l.z);
    tf32_split(v.w, h.w, l.w);
}

__device__ __forceinline__ void mma_m16n8k8(float c[4], const float a[4], const float b[2]) {
    asm volatile(
        "mma.sync.aligned.m16n8k8.row.col.f32.tf32.tf32.f32 "
        "{%0,%1,%2,%3}, {%4,%5,%6,%7}, {%8,%9}, {%0,%1,%2,%3};"
        : "+f"(c[0]), "+f"(c[1]), "+f"(c[2]), "+f"(c[3])
        : "r"(__float_as_uint(a[0])), "r"(__float_as_uint(a[1])),
          "r"(__float_as_uint(a[2])), "r"(__float_as_uint(a[3])),
          "r"(__float_as_uint(b[0])), "r"(__float_as_uint(b[1])));
}
__device__ __forceinline__ void mma3(float c[4], const float ah[4], const float al[4],
                                     const float bh[2], const float bl[2]) {
    mma_m16n8k8(c, ah, bh);
    mma_m16n8k8(c, al, bh);
    mma_m16n8k8(c, ah, bl);
}

// ---------------------------------------------------------------------------
// Kernel 1: projection GEMM with pre-split smem tiles (unchanged, passing).
// ---------------------------------------------------------------------------
#define PAP 36
#define PBP 136
#define PROJ_SMEM_FLOATS (128*PAP*2 + 32*PBP*2)
#define PROJ_SMEM_BYTES  (PROJ_SMEM_FLOATS * 4)

__global__ __launch_bounds__(256, 2) void proj_mma_kernel(
    const float* __restrict__ x, const float* __restrict__ WQ,
    const float* __restrict__ WK, const float* __restrict__ WV)
{
    extern __shared__ float ps[];
    float* AH = ps;
    float* AL = AH + 128 * PAP;
    float* BH = AL + 128 * PAP;
    float* BL = BH + 32 * PBP;

    const int tid = threadIdx.x;
    const int w   = tid >> 5, l = tid & 31;
    const int gid = l >> 2,  tig = l & 3;
    const int wr  = w >> 1,  wc  = w & 1;
    const int m0c = blockIdx.x * 128;
    const int n0c = blockIdx.y * 128;
    const float* __restrict__ W = (blockIdx.z == 0) ? WQ : (blockIdx.z == 1) ? WK : WV;
    float* __restrict__ C = (blockIdx.z == 0) ? g_Q : (blockIdx.z == 1) ? g_K : g_V;

    float acc[2][8][4];
#pragma unroll
    for (int mb = 0; mb < 2; mb++)
#pragma unroll
        for (int nb = 0; nb < 8; nb++)
#pragma unroll
            for (int i = 0; i < 4; i++) acc[mb][nb][i] = 0.f;

    for (int k0 = 0; k0 < DMODEL; k0 += 32) {
        __syncthreads();
#pragma unroll
        for (int p = 0; p < 4; p++) {
            int row = p * 32 + (tid >> 3);
            int f4  = (tid & 7) * 4;
            float4 v = *(const float4*)&x[(size_t)(m0c + row) * DMODEL + k0 + f4];
            float4 h, lo;
            split4(v, h, lo);
            *(float4*)&AH[row * PAP + f4] = h;
            *(float4*)&AL[row * PAP + f4] = lo;
        }
#pragma unroll
        for (int p = 0; p < 4; p++) {
            int kr = p * 8 + (tid >> 5);
            int f4 = (tid & 31) * 4;
            float4 v = *(const float4*)&W[(size_t)(k0 + kr) * DV + n0c + f4];
            float4 h, lo;
            split4(v, h, lo);
            *(float4*)&BH[kr * PBP + f4] = h;
            *(float4*)&BL[kr * PBP + f4] = lo;
        }
        __syncthreads();

#pragma unroll
        for (int ks = 0; ks < 4; ks++) {
            float ah[2][4], al[2][4];
#pragma unroll
            for (int mb = 0; mb < 2; mb++) {
                int base = (wr * 32 + mb * 16 + gid) * PAP + ks * 8 + tig;
                ah[mb][0] = AH[base];            al[mb][0] = AL[base];
                ah[mb][1] = AH[base + 8 * PAP];  al[mb][1] = AL[base + 8 * PAP];
                ah[mb][2] = AH[base + 4];        al[mb][2] = AL[base + 4];
                ah[mb][3] = AH[base + 8 * PAP + 4]; al[mb][3] = AL[base + 8 * PAP + 4];
            }
#pragma unroll
            for (int nb = 0; nb < 8; nb++) {
                int bb = (ks * 8 + tig) * PBP + wc * 64 + nb * 8 + gid;
                float bh[2], bl[2];
                bh[0] = BH[bb];            bl[0] = BL[bb];
                bh[1] = BH[bb + 4 * PBP];  bl[1] = BL[bb + 4 * PBP];
                mma3(acc[0][nb], ah[0], al[0], bh, bl);
                mma3(acc[1][nb], ah[1], al[1], bh, bl);
            }
        }
    }

#pragma unroll
    for (int mb = 0; mb < 2; mb++) {
        int r0 = m0c + wr * 32 + mb * 16 + gid;
#pragma unroll
        for (int nb = 0; nb < 8; nb++) {
            int cc = n0c + wc * 64 + nb * 8 + 2 * tig;
            *(float2*)&C[(size_t)r0 * DV + cc]       = make_float2(acc[mb][nb][0], acc[mb][nb][1]);
            *(float2*)&C[(size_t)(r0 + 8) * DV + cc] = make_float2(acc[mb][nb][2], acc[mb][nb][3]);
        }
    }
}

// ---------------------------------------------------------------------------
// Kernel 2: flash differential attention.
// BM=64 rows/CTA, BN=32 keys/tile, 512 threads (16 warps).
// K,V pre-split (hi/lo) in smem. Q unsplit (split on the fly, ALU hidden).
// P stored tf32-rounded; PV = P*Vh + P*Vl (2-term).
// QK: 16 warps = mat(2) x mrow(4: m16) x ncol(2: n16).
// PV: 16 warps = mat(2) x mhalf(2: m32) x colq(4: n64).
// ---------------------------------------------------------------------------
#define ABM 64
#define ABN 32
#define ATHR 512
#define QPITCH 132   // Q row pitch (gid-indexed rows: pitch % 32 == 4)
#define KPITCH 260   // K row pitch (gid-indexed rows)
#define VPITCH 264   // V row pitch (tig-indexed rows: pitch % 32 == 8)
#define PPITCH 36    // P row pitch (gid-indexed rows)

// float offsets
#define SQ   0                              // 2 mats x 64 x 132
#define SKH  (SQ + 2 * ABM * QPITCH)        // 32 x 260
#define SKL  (SKH + ABN * KPITCH)
#define SVH  (SKL + ABN * KPITCH)           // 32 x 264
#define SVL  (SVH + ABN * VPITCH)
#define SPH  (SVL + ABN * VPITCH)           // 2 mats x 64 x 36
#define SMR  (SPH + 2 * ABM * PPITCH)       // 128
#define SLR  (SMR + 128)
#define SFR  (SLR + 128)
#define SLAM (SFR + 128)
#define ATOT (SLAM + 4)
#define ATOT_BYTES (ATOT * 4)

__global__ __launch_bounds__(ATHR, 1) void diff_attn_mma(
    const float* __restrict__ lq1, const float* __restrict__ lq2,
    const float* __restrict__ lk1, const float* __restrict__ lk2,
    float* __restrict__ out)
{
    extern __shared__ float sm[];
    const int tid = threadIdx.x;
    const int w   = tid >> 5, l = tid & 31;
    const int gid = l >> 2,  tig = l & 3;
    const int b   = blockIdx.y;
    const int q0  = blockIdx.x * ABM;
    const float scale = 0.08838834764831845f;  // HD^-0.5

    // lambda scalar
    if (tid < 32) {
        float s1 = 0.f, s2 = 0.f;
        for (int i = l; i < HD; i += 32) {
            s1 += lq1[i] * lk1[i];
            s2 += lq2[i] * lk2[i];
        }
#pragma unroll
        for (int o = 16; o; o >>= 1) {
            s1 += __shfl_xor_sync(0xffffffffu, s1, o);
            s2 += __shfl_xor_sync(0xffffffffu, s2, o);
        }
        if (l == 0) {
            double li = 0.8 - 0.6 * exp(-3.6);
            sm[SLAM] = __expf(s1) + __expf(s2) + (float)li;
        }
    }
    if (tid < 128) { sm[SMR + tid] = -INFINITY; sm[SLR + tid] = 0.f; }

    // Q load + scale (unsplit); mats separated: dims<128 -> mat0, else mat1
    for (int idx = tid; idx < ABM * 64; idx += ATHR) {
        int r = idx >> 6, f4 = idx & 63;
        float4 v = *(const float4*)&g_Q[(size_t)(b * SEQ + q0 + r) * DV + f4 * 4];
        v.x *= scale; v.y *= scale; v.z *= scale; v.w *= scale;
        int matq = (f4 >= 32);
        int col  = (f4 - matq * 32) * 4;
        *(float4*)&sm[SQ + matq * (ABM * QPITCH) + r * QPITCH + col] = v;
    }

    // warp roles
    const int mat = w >> 3;
    const int wl  = w & 7;
    // QK: m-block (16 rows) and n-block (16 cols)
    const int qk_m = wl >> 1;       // 0..3
    const int qk_n = wl & 1;        // 0..1
    // PV: m-half (32 rows) and column quadrant (64 cols)
    const int pv_m = wl >> 2;       // 0..1
    const int pv_c = wl & 3;        // 0..3

    const int matQ = SQ + mat * (ABM * QPITCH);
    const int matP = SPH + mat * (ABM * PPITCH);
    const int kcol = mat * 128;

    float O[2][8][4];
#pragma unroll
    for (int mt = 0; mt < 2; mt++)
#pragma unroll
        for (int nt = 0; nt < 8; nt++)
#pragma unroll
            for (int i = 0; i < 4; i++) O[mt][nt][i] = 0.f;

    for (int j0 = 0; j0 < SEQ; j0 += ABN) {
        __syncthreads();  // previous PV done reading K/V
        // stage K (split) and V (split)
        for (int idx = tid; idx < ABN * 64; idx += ATHR) {
            int r = idx >> 6, f4 = idx & 63;
            size_t g = (size_t)(b * SEQ + j0 + r) * DV + f4 * 4;
            float4 kv = *(const float4*)&g_K[g];
            float4 vv = *(const float4*)&g_V[g];
            float4 h, lo;
            split4(kv, h, lo);
            *(float4*)&sm[SKH + r * KPITCH + f4 * 4] = h;
            *(float4*)&sm[SKL + r * KPITCH + f4 * 4] = lo;
            split4(vv, h, lo);
            *(float4*)&sm[SVH + r * VPITCH + f4 * 4] = h;
            *(float4*)&sm[SVL + r * VPITCH + f4 * 4] = lo;
        }
        __syncthreads();

        // QK^T: warp computes m16 x n16 of its matrix, k=128
        {
            float c[2][4] = {{0.f,0.f,0.f,0.f},{0.f,0.f,0.f,0.f}};
            const int qbase = matQ + (qk_m * 16 + gid) * QPITCH;
#pragma unroll
            for (int ks = 0; ks < 16; ks++) {
                int ab = qbase + ks * 8 + tig;
                float ah[4], al[4];
                tf32_split(sm[ab],                  ah[0], al[0]);
                tf32_split(sm[ab + 8 * QPITCH],     ah[1], al[1]);
                tf32_split(sm[ab + 4],              ah[2], al[2]);
                tf32_split(sm[ab + 8 * QPITCH + 4], ah[3], al[3]);
#pragma unroll
                for (int nb = 0; nb < 2; nb++) {
                    int bb = SKH + (qk_n * 16 + nb * 8 + gid) * KPITCH + kcol + ks * 8 + tig;
                    float bh[2], bl[2];
                    bh[0] = sm[bb];     bl[0] = sm[bb + (SKL - SKH)];
                    bh[1] = sm[bb + 4]; bl[1] = sm[bb + (SKL - SKH) + 4];
                    mma3(c[nb], ah, al, bh, bl);
                }
            }
            int rr = qk_m * 16 + gid;
#pragma unroll
            for (int nb = 0; nb < 2; nb++) {
                int cc = qk_n * 16 + nb * 8 + 2 * tig;
                *(float2*)&sm[matP + rr * PPITCH + cc]       = make_float2(c[nb][0], c[nb][1]);
                *(float2*)&sm[matP + (rr + 8) * PPITCH + cc] = make_float2(c[nb][2], c[nb][3]);
            }
        }
        __syncthreads();

        // online softmax: 512 threads = 2 mats x 64 rows x 4 lanes (8 cols each)
        {
            int smat = tid >> 8;
            int srow = (tid >> 2) & 63;
            int sub  = tid & 3;
            int base = SPH + smat * (ABM * PPITCH) + srow * PPITCH + sub * 8;
            float4 v0 = *(float4*)&sm[base];
            float4 v1 = *(float4*)&sm[base + 4];
            float tmax = fmaxf(fmaxf(fmaxf(v0.x, v0.y), fmaxf(v0.z, v0.w)),
                               fmaxf(fmaxf(v1.x, v1.y), fmaxf(v1.z, v1.w)));
            tmax = fmaxf(tmax, __shfl_xor_sync(0xffffffffu, tmax, 1));
            tmax = fmaxf(tmax, __shfl_xor_sync(0xffffffffu, tmax, 2));
            float mold = sm[SMR + smat * 64 + srow];
            float mnew = fmaxf(mold, tmax);
            float e0 = __expf(v0.x - mnew), e1 = __expf(v0.y - mnew);
            float e2 = __expf(v0.z - mnew), e3 = __expf(v0.w - mnew);
            float e4 = __expf(v1.x - mnew), e5 = __expf(v1.y - mnew);
            float e6 = __expf(v1.z - mnew), e7 = __expf(v1.w - mnew);
            float4 h0 = make_float4(tf32_round(e0), tf32_round(e1), tf32_round(e2), tf32_round(e3));
            float4 h1 = make_float4(tf32_round(e4), tf32_round(e5), tf32_round(e6), tf32_round(e7));
            *(float4*)&sm[base]     = h0;
            *(float4*)&sm[base + 4] = h1;
            float sum = (e0 + e1) + (e2 + e3) + (e4 + e5) + (e6 + e7);
            sum += __shfl_xor_sync(0xffffffffu, sum, 1);
            sum += __shfl_xor_sync(0xffffffffu, sum, 2);
            if (sub == 0) {
                float f = __expf(mold - mnew);
                sm[SMR + smat * 64 + srow] = mnew;
                sm[SLR + smat * 64 + srow] = sm[SLR + smat * 64 + srow] * f + sum;
                sm[SFR + smat * 64 + srow] = f;
            }
        }
        __syncthreads();

        // PV: warp = m32 x 64 cols of O{mat}; P is tf32 (A), V split (B)
        {
            float f0 = sm[SFR + mat * 64 + pv_m * 32 + gid];
            float f1 = sm[SFR + mat * 64 + pv_m * 32 + gid + 8];
            float f2 = sm[SFR + mat * 64 + pv_m * 32 + 16 + gid];
            float f3 = sm[SFR + mat * 64 + pv_m * 32 + 16 + gid + 8];
#pragma unroll
            for (int nt = 0; nt < 8; nt++) {
                O[0][nt][0] *= f0; O[0][nt][1] *= f0; O[0][nt][2] *= f1; O[0][nt][3] *= f1;
                O[1][nt][0] *= f2; O[1][nt][1] *= f2; O[1][nt][2] *= f3; O[1][nt][3] *= f3;
            }
#pragma unroll
            for (int kk = 0; kk < 4; kk++) {
                float a[2][4];
#pragma unroll
                for (int mt = 0; mt < 2; mt++) {
                    int ab = matP + (pv_m * 32 + mt * 16 + gid) * PPITCH + kk * 8 + tig;
                    a[mt][0] = sm[ab];
                    a[mt][1] = sm[ab + 8 * PPITCH];
                    a[mt][2] = sm[ab + 4];
                    a[mt][3] = sm[ab + 8 * PPITCH + 4];
                }
#pragma unroll
                for (int nt = 0; nt < 8; nt++) {
                    int col = pv_c * 64 + nt * 8 + gid;
                    int b0 = (kk * 8 + tig) * VPITCH + col;
                    int b1 = (kk * 8 + tig + 4) * VPITCH + col;
                    float bh[2], bl[2];
                    bh[0] = sm[SVH + b0]; bl[0] = sm[SVL + b0];
                    bh[1] = sm[SVH + b1]; bl[1] = sm[SVL + b1];
                    mma_m16n8k8(O[0][nt], a[0], bh);
                    mma_m16n8k8(O[0][nt], a[0], bl);
                    mma_m16n8k8(O[1][nt], a[1], bh);
                    mma_m16n8k8(O[1][nt], a[1], bl);
                }
            }
        }
    }
    __syncthreads();

    // epilogue: out = O1/l1 - lam*O2/l2; mat1 stages lam*O2/l2 in SQ scratch
    const float lam = sm[SLAM];
    if (mat == 1) {
#pragma unroll
        for (int mt = 0; mt < 2; mt++) {
            int ra = pv_m * 32 + mt * 16 + gid, rb = ra + 8;
            float sa = lam / sm[SLR + 64 + ra];
            float sb = lam / sm[SLR + 64 + rb];
#pragma unroll
            for (int nt = 0; nt < 8; nt++) {
                int cc = pv_c * 64 + nt * 8 + 2 * tig;
                *(float2*)&sm[SQ + ra * KPITCH + cc] =
                    make_float2(O[mt][nt][0] * sa, O[mt][nt][1] * sa);
                *(float2*)&sm[SQ + rb * KPITCH + cc] =
                    make_float2(O[mt][nt][2] * sb, O[mt][nt][3] * sb);
            }
        }
    }
    __syncthreads();
    if (mat == 0) {
#pragma unroll
        for (int mt = 0; mt < 2; mt++) {
            int ra = pv_m * 32 + mt * 16 + gid, rb = ra + 8;
            float ia = 1.f / sm[SLR + ra];
            float ib = 1.f / sm[SLR + rb];
            size_t basea = (size_t)(b * SEQ + q0 + ra) * DV;
            size_t baseb = (size_t)(b * SEQ + q0 + rb) * DV;
#pragma unroll
            for (int nt = 0; nt < 8; nt++) {
                int cc = pv_c * 64 + nt * 8 + 2 * tig;
                float2 s2 = *(float2*)&sm[SQ + ra * KPITCH + cc];
                *(float2*)&out[basea + cc] =
                    make_float2(O[mt][nt][0] * ia - s2.x, O[mt][nt][1] * ia - s2.y);
                s2 = *(float2*)&sm[SQ + rb * KPITCH + cc];
                *(float2*)&out[baseb + cc] =
                    make_float2(O[mt][nt][2] * ib - s2.x, O[mt][nt][3] * ib - s2.y);
            }
        }
    }
}

// ---------------------------------------------------------------------------
// Launch
// ---------------------------------------------------------------------------
extern "C" void kernel_launch(void* const* d_in, const int* in_sizes, int n_in,
                              void* d_out, int out_size)
{
    const float* x   = (const float*)d_in[0];
    const float* WQ  = (const float*)d_in[1];
    const float* WK  = (const float*)d_in[2];
    const float* WV  = (const float*)d_in[3];
    const float* lq1 = (const float*)d_in[4];
    const float* lq2 = (const float*)d_in[5];
    const float* lk1 = (const float*)d_in[6];
    const float* lk2 = (const float*)d_in[7];
    float* out = (float*)d_out;

    cudaFuncSetAttribute(proj_mma_kernel,
                         cudaFuncAttributeMaxDynamicSharedMemorySize, PROJ_SMEM_BYTES);
    dim3 pgrid(MROWS / 128, DV / 128, 3);
    proj_mma_kernel<<<pgrid, 256, PROJ_SMEM_BYTES>>>(x, WQ, WK, WV);

    cudaFuncSetAttribute(diff_attn_mma,
                         cudaFuncAttributeMaxDynamicSharedMemorySize, ATOT_BYTES);
    dim3 agrid(SEQ / ABM, BATCH);
    diff_attn_mma<<<agrid, ATHR, ATOT_BYTES>>>(lq1, lq2, lk1, lk2, out);
}